// round 11
// baseline (speedup 1.0000x reference)
#include <cuda_runtime.h>
#include <cuda_fp16.h>
#include <cstdint>

// ---------------------------------------------------------------------------
// Problem constants
// ---------------------------------------------------------------------------
#define KDIM 256
#define NDIM 256
#define KC   64                    // K chunk
#define NCHUNK (KDIM / KC)
#define NTHR 256                   // 8 warps
#define BM 64                      // CTA M tile (2 CTAs/SM)

// SMEM layout (bytes)
#define OFF_STAB  0                              // 8 x float4 = 128B
#define OFF_CTAB  128                            // padded (c0,c1) pairs
#define OFF_A     3072                           // 1024-aligned
#define A_BUF     (BM * 128)                     // 8192
#define SMEM_TOTAL (OFF_A + 2 * A_BUF)           // 19456

// ---------------------------------------------------------------------------
// Prologue outputs
// ---------------------------------------------------------------------------
// B in mma-fragment order: [chunk][ks][ntile(16)][lane(32)] -> uint4 (b0..b3)
__device__ __align__(16) uint4 g_Bfrag[NCHUNK * 4 * 16 * 32];   // 128KB
__device__ __align__(16) unsigned char g_ctab[2432];            // padded c0c1
__device__ __align__(16) float4 g_stab[8];                      // segment cubics

// ---------------------------------------------------------------------------
// helpers
// ---------------------------------------------------------------------------
__device__ __forceinline__ uint32_t smem_u32(const void* p) {
    uint32_t a;
    asm("{ .reg .u64 t; cvta.to.shared.u64 t, %1; cvt.u32.u64 %0, t; }" : "=r"(a) : "l"(p));
    return a;
}

__device__ __forceinline__ void ldsm_x4(uint32_t& r0, uint32_t& r1, uint32_t& r2,
                                        uint32_t& r3, uint32_t addr) {
    asm volatile("ldmatrix.sync.aligned.m8n8.x4.shared.b16 {%0,%1,%2,%3}, [%4];"
                 : "=r"(r0), "=r"(r1), "=r"(r2), "=r"(r3) : "r"(addr));
}

__device__ __forceinline__ void mma_fp16(float* c, const uint32_t* a,
                                         uint32_t b0, uint32_t b1) {
    asm volatile(
        "mma.sync.aligned.m16n8k16.row.col.f32.f16.f16.f32 "
        "{%0,%1,%2,%3}, {%4,%5,%6,%7}, {%8,%9}, {%0,%1,%2,%3};"
        : "+f"(c[0]), "+f"(c[1]), "+f"(c[2]), "+f"(c[3])
        : "r"(a[0]), "r"(a[1]), "r"(a[2]), "r"(a[3]), "r"(b0), "r"(b1));
}

__device__ __forceinline__ uint32_t pack_h2(float a0, float a1) {
    __half2 h = __floats2half2_rn(a0, a1);
    return *reinterpret_cast<uint32_t*>(&h);
}

// padded (c0,c1) offset: one 16B granule holds pairs for channels {k, k+1}
__device__ __host__ __forceinline__ int ctab_off(int k) {
    return k * 8 + (k >> 4) * 16;
}

// ---------------------------------------------------------------------------
// Prologue: B fragment image + c0c1 pairs + segment-cubic table
// ---------------------------------------------------------------------------
__global__ void kan_prologue(const float* __restrict__ ic, const float* __restrict__ oc) {
    if (blockIdx.x < 32) {
        // one thread = one uint4 fragment record
        int gid  = blockIdx.x * 256 + threadIdx.x;   // 0..8191
        int lane = gid & 31;
        int t    = (gid >> 5) & 15;                   // n-tile (16 rows)
        int ks   = (gid >> 9) & 3;                    // kstep within chunk
        int c    = (gid >> 11) & 3;                   // chunk
        uint32_t h[4];
#pragma unroll
        for (int m = 0; m < 4; m++) {
            int n  = t * 16 + (m & 1) * 8 + (lane >> 2);
            int kk = c * KC + ks * 16 + (m >> 1) * 8 + (lane & 3) * 2;
            h[m] = pack_h2(oc[n * KDIM + kk], oc[n * KDIM + kk + 1]);
        }
        g_Bfrag[gid] = make_uint4(h[0], h[1], h[2], h[3]);
    } else {
        int k = threadIdx.x;
        float c0 = ic[k * 5 + 0];
        float c1 = ic[k * 5 + 1];
        *(float2*)(g_ctab + ctab_off(k)) = make_float2(c0, c1);
        if (k < 8) {
            const float P[4][4] = {
                {0.f, 0.f, 0.f,  1.f},
                {1.f, 3.f, 3.f, -3.f},
                {4.f, 0.f, -6.f, 3.f},
                {1.f, -3.f, 3.f, -1.f}
            };
            float4 s = make_float4(0.f, 0.f, 0.f, 0.f);
            if (k >= 1 && k <= 4) {
                const float s6 = 1.0f / 6.0f;
                int m = k - 1;
                s = make_float4(P[m][0] * s6, P[m][1] * s6, P[m][2] * s6, P[m][3] * s6);
            }
            g_stab[k] = s;
        }
    }
}

// ---------------------------------------------------------------------------
// Hot-path activation (R10 variant, conflict-free)
// ---------------------------------------------------------------------------
__device__ __forceinline__ float kan_act2(float xv, float c0, float c1,
                                          const float4* __restrict__ stab) {
    float e2 = __expf(2.0f * xv);
    float t  = 1.0f - __fdividef(2.0f, e2 + 1.0f);   // tanh
    float v  = fmaf(t, 3.5f, 3.5f);                   // (t+1)/h, in [0,7]
    int j = (int)v;
    j = j > 5 ? 5 : j;
    float u = v - (float)j;
    float4 sB = stab[j];        // B31 segment cubic
    float4 sA = stab[j + 1];    // B30 segment cubic
    float b30 = fmaf(fmaf(fmaf(sA.w, u, sA.z), u, sA.y), u, sA.x);
    float b31 = fmaf(fmaf(fmaf(sB.w, u, sB.z), u, sB.y), u, sB.x);
    return fmaf(c0, b30, c1 * b31);
}

__device__ __forceinline__ void act16(const float* av, int kb, const char* ctab,
                                      const float4* __restrict__ stab, float* r) {
#pragma unroll
    for (int p = 0; p < 8; p++) {
        int k0 = kb + 2 * p;
        float4 cg = *(const float4*)(ctab + ctab_off(k0));
        r[2 * p]     = kan_act2(av[2 * p],     cg.x, cg.y, stab);
        r[2 * p + 1] = kan_act2(av[2 * p + 1], cg.z, cg.w, stab);
    }
}

// ---------------------------------------------------------------------------
// Main: CTA computes C[64 x 256] = act(X[64 x 256]) @ W^T, fp16 HMMA.
// B comes straight from gmem in fragment order (L2-hot); A via smem.
// ---------------------------------------------------------------------------
__global__ void __launch_bounds__(NTHR, 2)
kan_main(const float* __restrict__ x, float* __restrict__ out) {
    extern __shared__ __align__(1024) char smem[];
    const int tid = threadIdx.x;
    const int wid = tid >> 5;
    const int lid = tid & 31;
    const int m0  = blockIdx.x * BM;

    const uint32_t sbase = smem_u32(smem);

    // warp tile: 32 (M) x 64 (N); 8 warps = 2 (M) x 4 (N)
    const int wm    = (wid >> 2) * 32;
    const int tbase = (wid & 3) * 4;     // n-tile base (4 tiles of 16)

    // ---- stage tables ----
    if (tid < 160) {
        if (tid < 8)
            ((float4*)(smem + OFF_STAB))[tid] = g_stab[tid];
        else
            ((float4*)(smem + OFF_CTAB))[tid - 8] = ((const float4*)g_ctab)[tid - 8];
    }

    // ---- x chunk 0 ----
    const int arow = tid >> 2;          // 0..63
    const int aq   = tid & 3;           // k-quarter (16 elems)
    const float4* xbase = (const float4*)(x + (size_t)(m0 + arow) * KDIM + aq * 16);
    float4 xv0 = xbase[0], xv1 = xbase[1], xv2 = xbase[2], xv3 = xbase[3];

    __syncthreads();                    // tables visible
    const float4* stab = (const float4*)(smem + OFF_STAB);
    const char*   ctab = smem + OFF_CTAB;

    const int swg0 = ((aq * 2)     ^ (arow & 7)) << 4;
    const int swg1 = ((aq * 2 + 1) ^ (arow & 7)) << 4;

    // ---- act(0) -> A buf 0 ----
    {
        float av[16] = {xv0.x, xv0.y, xv0.z, xv0.w, xv1.x, xv1.y, xv1.z, xv1.w,
                        xv2.x, xv2.y, xv2.z, xv2.w, xv3.x, xv3.y, xv3.z, xv3.w};
        float r[16];
        act16(av, aq * 16, ctab, stab, r);
        char* ad = smem + OFF_A + arow * 128;
        *(uint4*)(ad + swg0) = make_uint4(pack_h2(r[0], r[1]),  pack_h2(r[2], r[3]),
                                          pack_h2(r[4], r[5]),  pack_h2(r[6], r[7]));
        *(uint4*)(ad + swg1) = make_uint4(pack_h2(r[8], r[9]),  pack_h2(r[10], r[11]),
                                          pack_h2(r[12], r[13]), pack_h2(r[14], r[15]));
    }

    float acc[2][8][4];
#pragma unroll
    for (int mt = 0; mt < 2; mt++)
#pragma unroll
        for (int nt = 0; nt < 8; nt++)
#pragma unroll
            for (int e = 0; e < 4; e++) acc[mt][nt][e] = 0.0f;

    const int lr   = lid & 15;          // ldmatrix row within 16
    const int lhal = lid >> 4;          // k-granule half

#pragma unroll
    for (int c = 0; c < NCHUNK; c++) {
        const int s = c & 1;
        __syncthreads();                // A(c) visible; A(alt) readers done

        // ---- prefetch x(c+1) ----
        if (c < NCHUNK - 1) {
            const float4* xp = xbase + (c + 1) * (KC / 4);
            xv0 = xp[0]; xv1 = xp[1]; xv2 = xp[2]; xv3 = xp[3];
        }

        // ---- MMA(c): 4 ksteps; B fragments straight from gmem (L2-hot) ----
        const uint32_t aBase = sbase + OFF_A + s * A_BUF;
#pragma unroll
        for (int ks = 0; ks < 4; ks++) {
            // B fragment loads: coalesced 512B per warp, barrier-independent
            uint4 bb[4];
#pragma unroll
            for (int np = 0; np < 4; np++) {
                int idx = (((c * 4 + ks) * 16) + tbase + np) * 32 + lid;
                bb[np] = __ldg(&g_Bfrag[idx]);
            }
            const int g = ks * 2 + lhal;
            uint32_t a[2][4];
#pragma unroll
            for (int mt = 0; mt < 2; mt++) {
                int r = wm + mt * 16 + lr;
                uint32_t off = (uint32_t)(r * 128 + ((g ^ (r & 7)) << 4));
                ldsm_x4(a[mt][0], a[mt][1], a[mt][2], a[mt][3], aBase + off);
            }
#pragma unroll
            for (int np = 0; np < 4; np++) {
#pragma unroll
                for (int mt = 0; mt < 2; mt++) {
                    mma_fp16(acc[mt][2 * np + 0], a[mt], bb[np].x, bb[np].z);
                    mma_fp16(acc[mt][2 * np + 1], a[mt], bb[np].y, bb[np].w);
                }
            }
        }

        // ---- act(c+1) -> other A buffer ----
        if (c < NCHUNK - 1) {
            float av[16] = {xv0.x, xv0.y, xv0.z, xv0.w, xv1.x, xv1.y, xv1.z, xv1.w,
                            xv2.x, xv2.y, xv2.z, xv2.w, xv3.x, xv3.y, xv3.z, xv3.w};
            float r[16];
            act16(av, (c + 1) * KC + aq * 16, ctab, stab, r);
            char* ad = smem + OFF_A + (s ^ 1) * A_BUF + arow * 128;
            *(uint4*)(ad + swg0) = make_uint4(pack_h2(r[0], r[1]),  pack_h2(r[2], r[3]),
                                              pack_h2(r[4], r[5]),  pack_h2(r[6], r[7]));
            *(uint4*)(ad + swg1) = make_uint4(pack_h2(r[8], r[9]),  pack_h2(r[10], r[11]),
                                              pack_h2(r[12], r[13]), pack_h2(r[14], r[15]));
        }
    }

    // ---- epilogue: direct fp32 stores from accumulators ----
    {
        const int rq = lid >> 2;            // 0..7
        const int cq = (lid & 3) * 2;       // 0,2,4,6
        const int wn = (wid & 3) * 64;
#pragma unroll
        for (int mt = 0; mt < 2; mt++) {
            int row = m0 + wm + mt * 16 + rq;
#pragma unroll
            for (int nt = 0; nt < 8; nt++) {
                int col = wn + nt * 8 + cq;
                float2 v0 = make_float2(acc[mt][nt][0], acc[mt][nt][1]);
                float2 v1 = make_float2(acc[mt][nt][2], acc[mt][nt][3]);
                *(float2*)(out + (size_t)row * NDIM + col)       = v0;
                *(float2*)(out + (size_t)(row + 8) * NDIM + col) = v1;
            }
        }
    }
}

// ---------------------------------------------------------------------------
extern "C" void kernel_launch(void* const* d_in, const int* in_sizes, int n_in,
                              void* d_out, int out_size) {
    const float* x  = (const float*)d_in[0];   // [B,S,256] fp32
    const float* ic = (const float*)d_in[1];   // [256,5]   fp32
    const float* oc = (const float*)d_in[2];   // [256,256] fp32
    float* out = (float*)d_out;

    const int M = in_sizes[0] / KDIM;          // 65536

    cudaFuncSetAttribute(kan_main, cudaFuncAttributeMaxDynamicSharedMemorySize, SMEM_TOTAL);

    kan_prologue<<<33, 256>>>(ic, oc);
    kan_main<<<M / BM, NTHR, SMEM_TOTAL>>>(x, out);
}